// round 4
// baseline (speedup 1.0000x reference)
#include <cuda_runtime.h>
#include <cuda_bf16.h>
#include <math.h>

// ---------------- problem constants ----------------
#define TT   8
#define NC   512
#define NT   512
#define DD   256
#define HH   8
#define LBL  3
#define NBF  1419
#define EPS_ 1e-4f
#define DN   0.25f          // 256^-0.25
#define DN2  0.0625f        // DN*DN
#define RATIO 0.026549364f  // 1419^-0.5

// ---------------- scratch (device globals; no allocations allowed) ----------------
__device__ float g_xc  [TT*NC*(DD+LBL)];        // concat [4096,259]
__device__ float g_h1  [TT*NC*DD];
__device__ float g_h2  [TT*NC*DD];
__device__ float g_cf  [TT*NC*DD];
__device__ float g_k   [TT*HH*NC*DD];
__device__ float g_v   [TT*HH*NC*DD];
__device__ float g_q   [TT*HH*NT*DD];
__device__ float g_qp  [(long long)TT*HH*NT*NBF];
__device__ float g_kp  [(long long)TT*HH*NC*NBF];
__device__ float g_ksum[TT*HH*NBF];
__device__ float g_kmxp[TT*HH*8];
__device__ float g_dinv[TT*HH*NT];
__device__ float g_ctx [(long long)TT*HH*NBF*DD];
__device__ float g_om  [TT*NT*HH*DD];           // merged [4096,2048]
__device__ float g_rep [TT*NT*DD];

// ---------------- generic tiled fp32 GEMM ----------------
// C[m,n] = alpha * sum_k A(m,k) * B(k,n) (+bias[n]) (relu) (*rowScale[m])
// TA: A stored [K,M] (A[k*lda+m]); else A[m*lda+k]
// TB: B stored [N,K] (B[n*ldb+k]); else B[k*ldb+n]
#define TM_ 64
#define TN_ 64
#define TK_ 16

template<bool TA, bool TB>
__global__ __launch_bounds__(256)
void gemm_kernel(const float* __restrict__ A, const float* __restrict__ B,
                 float* __restrict__ C,
                 int M, int N, int K, int lda, int ldb, int ldc, int cstride,
                 long long sA, long long sB, long long sC,
                 const float* __restrict__ bias, long long sBias,
                 const float* __restrict__ rowScale, long long sRS,
                 float alpha, int relu)
{
    __shared__ float As[TK_][TM_ + 1];
    __shared__ float Bs[TK_][TN_ + 1];

    int z = blockIdx.z;
    A += z * sA; B += z * sB; C += z * sC;
    const float* bptr = bias     ? bias     + z * sBias : nullptr;
    const float* rptr = rowScale ? rowScale + z * sRS   : nullptr;

    int tid = threadIdx.x;
    int tr = tid >> 4;       // 0..15
    int tc = tid & 15;       // 0..15
    int row0 = blockIdx.y * TM_;
    int col0 = blockIdx.x * TN_;

    float acc[4][4];
#pragma unroll
    for (int i = 0; i < 4; i++)
#pragma unroll
        for (int j = 0; j < 4; j++) acc[i][j] = 0.f;

    for (int k0 = 0; k0 < K; k0 += TK_) {
        // ---- load A tile: As[k][m] ----
#pragma unroll
        for (int it = 0; it < 4; ++it) {
            int idx = tid + it * 256;
            if (TA) {
                int kk = idx >> 6, m = idx & 63;
                int gm = row0 + m, gk = k0 + kk;
                As[kk][m] = (gm < M && gk < K) ? A[(long long)gk * lda + gm] : 0.f;
            } else {
                int m = idx >> 4, kk = idx & 15;
                int gm = row0 + m, gk = k0 + kk;
                As[kk][m] = (gm < M && gk < K) ? A[(long long)gm * lda + gk] : 0.f;
            }
        }
        // ---- load B tile: Bs[k][n] ----
#pragma unroll
        for (int it = 0; it < 4; ++it) {
            int idx = tid + it * 256;
            if (TB) {
                int n = idx >> 4, kk = idx & 15;
                int gn = col0 + n, gk = k0 + kk;
                Bs[kk][n] = (gn < N && gk < K) ? B[(long long)gn * ldb + gk] : 0.f;
            } else {
                int kk = idx >> 6, n = idx & 63;
                int gn = col0 + n, gk = k0 + kk;
                Bs[kk][n] = (gn < N && gk < K) ? B[(long long)gk * ldb + gn] : 0.f;
            }
        }
        __syncthreads();
#pragma unroll
        for (int kk = 0; kk < TK_; ++kk) {
            float a[4], b[4];
#pragma unroll
            for (int i = 0; i < 4; i++) a[i] = As[kk][tr * 4 + i];
#pragma unroll
            for (int j = 0; j < 4; j++) b[j] = Bs[kk][tc * 4 + j];
#pragma unroll
            for (int i = 0; i < 4; i++)
#pragma unroll
                for (int j = 0; j < 4; j++) acc[i][j] = fmaf(a[i], b[j], acc[i][j]);
        }
        __syncthreads();
    }

#pragma unroll
    for (int i = 0; i < 4; i++) {
        int r = row0 + tr * 4 + i;
        if (r >= M) continue;
        float rs = rptr ? rptr[r] : 1.f;
#pragma unroll
        for (int j = 0; j < 4; j++) {
            int c = col0 + tc * 4 + j;
            if (c >= N) continue;
            float v = acc[i][j] * alpha;
            if (bptr) v += bptr[c];
            if (relu) v = fmaxf(v, 0.f);
            v *= rs;
            C[(long long)r * ldc + (long long)c * cstride] = v;
        }
    }
}

// ---------------- reductions ----------------
__device__ __forceinline__ float block_reduce_sum(float v) {
    __shared__ float sh[32];
    int lane = threadIdx.x & 31, w = threadIdx.x >> 5;
#pragma unroll
    for (int o = 16; o; o >>= 1) v += __shfl_xor_sync(0xffffffffu, v, o);
    __syncthreads();
    if (lane == 0) sh[w] = v;
    __syncthreads();
    float r = (threadIdx.x < (blockDim.x >> 5)) ? sh[threadIdx.x] : 0.f;
    if (w == 0) {
#pragma unroll
        for (int o = 16; o; o >>= 1) r += __shfl_xor_sync(0xffffffffu, r, o);
        if (lane == 0) sh[0] = r;
    }
    __syncthreads();
    return sh[0];
}

__device__ __forceinline__ float block_reduce_max(float v) {
    __shared__ float sh[32];
    int lane = threadIdx.x & 31, w = threadIdx.x >> 5;
#pragma unroll
    for (int o = 16; o; o >>= 1) v = fmaxf(v, __shfl_xor_sync(0xffffffffu, v, o));
    __syncthreads();
    if (lane == 0) sh[w] = v;
    __syncthreads();
    float r = (threadIdx.x < (blockDim.x >> 5)) ? sh[threadIdx.x] : -INFINITY;
    if (w == 0) {
#pragma unroll
        for (int o = 16; o; o >>= 1) r = fmaxf(r, __shfl_xor_sync(0xffffffffu, r, o));
        if (lane == 0) sh[0] = r;
    }
    __syncthreads();
    return sh[0];
}

// ---------------- elementwise / feature kernels ----------------
__global__ void concat_kernel(const float* __restrict__ x, const float* __restrict__ lbl,
                              float* __restrict__ out) {
    int r = blockIdx.x, tid = threadIdx.x;  // 256 threads
    out[(long long)r * 259 + tid] = x[(long long)r * 256 + tid];
    if (tid < LBL) out[(long long)r * 259 + 256 + tid] = lbl[(long long)r * LBL + tid];
}

// queries: per-row max over F, diag from q row; in-place on dd
__global__ void qfeat_kernel(float* __restrict__ dd, const float* __restrict__ q) {
    long long row = blockIdx.x;
    const float* qr = q + row * DD;
    float* d = dd + row * NBF;
    int tid = threadIdx.x;  // 256
    float qv = qr[tid];
    float diag = 0.5f * block_reduce_sum(qv * qv) * DN2;
    float mx = -INFINITY;
    for (int f = tid; f < NBF; f += 256) mx = fmaxf(mx, d[f]);
    mx = block_reduce_max(mx);
    float sub = diag + mx;
    for (int f = tid; f < NBF; f += 256) d[f] = RATIO * (expf(d[f] - sub) + EPS_);
}

// keys stage 1: partial max per (t,h) over (n,f); 8 n-chunks of 64 rows
__global__ void kmax_kernel(const float* __restrict__ dd, float* __restrict__ kmaxp) {
    int th = blockIdx.y, chunk = blockIdx.x;
    const float* base = dd + ((long long)th * NC + (long long)chunk * 64) * NBF;
    float mx = -INFINITY;
    for (long long i = threadIdx.x; i < (long long)64 * NBF; i += blockDim.x)
        mx = fmaxf(mx, base[i]);
    mx = block_reduce_max(mx);
    if (threadIdx.x == 0) kmaxp[th * 8 + chunk] = mx;
}

// keys stage 2: apply exp with global-(t,h) max; in-place on dd
__global__ void kfeat_kernel(float* __restrict__ dd, const float* __restrict__ k,
                             const float* __restrict__ kmaxp) {
    long long row = blockIdx.x;
    int th = (int)(row >> 9);
    const float* kr = k + row * DD;
    float* d = dd + row * NBF;
    int tid = threadIdx.x;
    float kv = kr[tid];
    float diag = 0.5f * block_reduce_sum(kv * kv) * DN2;
    float mx = -INFINITY;
#pragma unroll
    for (int c = 0; c < 8; c++) mx = fmaxf(mx, kmaxp[th * 8 + c]);
    float sub = diag + mx;
    for (int f = tid; f < NBF; f += 256) d[f] = RATIO * (expf(d[f] - sub) + EPS_);
}

// ksum[th][f] = sum_n kp[th][n][f]
__global__ void ksum_kernel(const float* __restrict__ kp, float* __restrict__ ksum) {
    int th = blockIdx.x;
    const float* base = kp + (long long)th * NC * NBF;
    for (int f = threadIdx.x; f < NBF; f += blockDim.x) {
        float s = 0.f;
        for (int n = 0; n < NC; n++) s += base[(long long)n * NBF + f];
        ksum[(long long)th * NBF + f] = s;
    }
}

// d_inv[row] = 1 / dot(qp[row], ksum[th])
__global__ void dinv_kernel(const float* __restrict__ qp, const float* __restrict__ ksum,
                            float* __restrict__ dinv) {
    long long row = blockIdx.x;
    int th = (int)(row >> 9);
    const float* qr = qp + row * NBF;
    const float* ks = ksum + (long long)th * NBF;
    float s = 0.f;
    for (int f = threadIdx.x; f < NBF; f += 256) s += qr[f] * ks[f];
    s = block_reduce_sum(s);
    if (threadIdx.x == 0) dinv[row] = 1.0f / s;
}

// ---------------- host side ----------------
static float* symaddr(const void* sym) {
    void* p = nullptr;
    cudaGetSymbolAddress(&p, sym);
    return (float*)p;
}

static void gemm(bool ta, bool tb,
                 const float* A, const float* B, float* C,
                 int M, int N, int K, int lda, int ldb, int ldc, int cstride,
                 long long sA, long long sB, long long sC,
                 const float* bias, long long sBias,
                 const float* rs, long long sRS,
                 float alpha, int relu, int batch)
{
    dim3 grid((N + TN_ - 1) / TN_, (M + TM_ - 1) / TM_, batch), blk(256);
    if (!ta && !tb)
        gemm_kernel<false, false><<<grid, blk>>>(A, B, C, M, N, K, lda, ldb, ldc, cstride,
                                                 sA, sB, sC, bias, sBias, rs, sRS, alpha, relu);
    else if (!ta && tb)
        gemm_kernel<false, true><<<grid, blk>>>(A, B, C, M, N, K, lda, ldb, ldc, cstride,
                                                sA, sB, sC, bias, sBias, rs, sRS, alpha, relu);
    else if (ta && !tb)
        gemm_kernel<true, false><<<grid, blk>>>(A, B, C, M, N, K, lda, ldb, ldc, cstride,
                                                sA, sB, sC, bias, sBias, rs, sRS, alpha, relu);
    else
        gemm_kernel<true, true><<<grid, blk>>>(A, B, C, M, N, K, lda, ldb, ldc, cstride,
                                               sA, sB, sC, bias, sBias, rs, sRS, alpha, relu);
}

extern "C" void kernel_launch(void* const* d_in, const int* in_sizes, int n_in,
                              void* d_out, int out_size) {
    (void)in_sizes; (void)n_in; (void)out_size;
    const float* x_ctx = (const float*)d_in[0];
    const float* label = (const float*)d_in[1];
    const float* x_tgt = (const float*)d_in[2];
    const float* W1 = (const float*)d_in[3];  const float* b1 = (const float*)d_in[4];
    const float* W2 = (const float*)d_in[5];  const float* b2 = (const float*)d_in[6];
    const float* W3 = (const float*)d_in[7];  const float* b3 = (const float*)d_in[8];
    const float* Wk = (const float*)d_in[9];  const float* bk = (const float*)d_in[10];
    const float* Wv = (const float*)d_in[11]; const float* bv = (const float*)d_in[12];
    const float* Wq = (const float*)d_in[13]; const float* bq = (const float*)d_in[14];
    const float* Wo = (const float*)d_in[15]; const float* bo = (const float*)d_in[16];
    const float* Wmu = (const float*)d_in[17]; const float* bmu = (const float*)d_in[18];
    const float* proj = (const float*)d_in[19];
    float* out = (float*)d_out;

    float* xc   = symaddr(g_xc);
    float* h1   = symaddr(g_h1);
    float* h2   = symaddr(g_h2);
    float* cf   = symaddr(g_cf);
    float* kbuf = symaddr(g_k);
    float* vbuf = symaddr(g_v);
    float* qbuf = symaddr(g_q);
    float* qp   = symaddr(g_qp);
    float* kp   = symaddr(g_kp);
    float* ksum = symaddr(g_ksum);
    float* kmxp = symaddr(g_kmxp);
    float* dinv = symaddr(g_dinv);
    float* ctx  = symaddr(g_ctx);
    float* om   = symaddr(g_om);
    float* rep  = symaddr(g_rep);

    const int M_ALL = TT * NC;  // 4096

    // 1) task encoder MLP
    concat_kernel<<<M_ALL, 256>>>(x_ctx, label, xc);
    gemm(0, 0, xc, W1, h1, M_ALL, DD, DD + LBL, DD + LBL, DD, DD, 1, 0, 0, 0,
         b1, 0, nullptr, 0, 1.f, 1, 1);
    gemm(0, 0, h1, W2, h2, M_ALL, DD, DD, DD, DD, DD, 1, 0, 0, 0,
         b2, 0, nullptr, 0, 1.f, 1, 1);
    gemm(0, 0, h2, W3, cf, M_ALL, DD, DD, DD, DD, DD, 1, 0, 0, 0,
         b3, 0, nullptr, 0, 1.f, 1, 1);

    // 2) per-head k/v/q projections (layout [t,h,n,e]); batch over t, loop over h
    for (int h = 0; h < HH; h++) {
        long long wo = (long long)h * DD * DD;
        gemm(0, 0, x_ctx, Wk + wo, kbuf + (long long)h * NC * DD,
             NC, DD, DD, DD, DD, DD, 1,
             (long long)NC * DD, 0, (long long)HH * NC * DD,
             bk + h * DD, 0, nullptr, 0, 1.f, 0, TT);
        gemm(0, 0, cf, Wv + wo, vbuf + (long long)h * NC * DD,
             NC, DD, DD, DD, DD, DD, 1,
             (long long)NC * DD, 0, (long long)HH * NC * DD,
             bv + h * DD, 0, nullptr, 0, 1.f, 0, TT);
        gemm(0, 0, x_tgt, Wq + wo, qbuf + (long long)h * NT * DD,
             NT, DD, DD, DD, DD, DD, 1,
             (long long)NT * DD, 0, (long long)HH * NT * DD,
             bq + h * DD, 0, nullptr, 0, 1.f, 0, TT);
    }

    // 3) FAVOR+ feature projections: dd = (x * dn) @ proj^T, batch over (t,h)
    gemm(0, 1, qbuf, proj, qp, NT, NBF, DD, DD, DD, NBF, 1,
         (long long)NT * DD, 0, (long long)NT * NBF,
         nullptr, 0, nullptr, 0, DN, 0, TT * HH);
    gemm(0, 1, kbuf, proj, kp, NC, NBF, DD, DD, DD, NBF, 1,
         (long long)NC * DD, 0, (long long)NC * NBF,
         nullptr, 0, nullptr, 0, DN, 0, TT * HH);

    // 4) softmax-kernel transforms
    kmax_kernel<<<dim3(8, TT * HH), 256>>>(kp, kmxp);
    qfeat_kernel<<<TT * HH * NT, 256>>>(qp, qbuf);
    kfeat_kernel<<<TT * HH * NC, 256>>>(kp, kbuf, kmxp);
    ksum_kernel<<<TT * HH, 512>>>(kp, ksum);
    dinv_kernel<<<TT * HH * NT, 256>>>(qp, ksum, dinv);

    // 5) ctx[t,h] = kp^T @ v : [1419,256] = [512,1419]^T @ [512,256], batch 64
    gemm(1, 0, kp, vbuf, ctx, NBF, DD, NC, NBF, DD, DD, 1,
         (long long)NC * NBF, (long long)NC * DD, (long long)NBF * DD,
         nullptr, 0, nullptr, 0, 1.f, 0, TT * HH);

    // 6) out = (qp @ ctx) * d_inv, stored head-interleaved into om[t,n,e*H+h]
    for (int h = 0; h < HH; h++) {
        gemm(0, 0, qp + (long long)h * NT * NBF, ctx + (long long)h * NBF * DD, om + h,
             NT, DD, NBF, NBF, DD, HH * DD, HH,
             (long long)HH * NT * NBF, (long long)HH * NBF * DD, (long long)NT * HH * DD,
             nullptr, 0, dinv + (long long)h * NT, (long long)HH * NT, 1.f, 0, TT);
    }

    // 7) rep = om @ Wo + bo ; mu = rep @ Wmu + bmu
    gemm(0, 0, om, Wo, rep, M_ALL, DD, HH * DD, HH * DD, DD, DD, 1,
         0, 0, 0, bo, 0, nullptr, 0, 1.f, 0, 1);
    gemm(0, 0, rep, Wmu, out, M_ALL, DD, DD, DD, DD, DD, 1,
         0, 0, 0, bmu, 0, nullptr, 0, 1.f, 0, 1);
}

// round 5
// speedup vs baseline: 1.0050x; 1.0050x over previous
#include <cuda_runtime.h>
#include <cuda_bf16.h>
#include <math.h>

// ---------------- problem constants ----------------
#define TT   8
#define NC   512
#define NT   512
#define DD   256
#define HH   8
#define LBL  3
#define NBF  1419
#define EPS_ 1e-4f
#define DN   0.25f          // 256^-0.25
#define DN2  0.0625f        // DN*DN
#define RATIO 0.026549364f  // 1419^-0.5

// ---------------- scratch (device globals; no allocations allowed) ----------------
__device__ float g_xc  [TT*NC*(DD+LBL)];        // concat [4096,259]
__device__ float g_h1  [TT*NC*DD];
__device__ float g_h2  [TT*NC*DD];
__device__ float g_cf  [TT*NC*DD];
__device__ float g_k   [TT*HH*NC*DD];
__device__ float g_v   [TT*HH*NC*DD];
__device__ float g_q   [TT*HH*NT*DD];
__device__ float g_qp  [(long long)TT*HH*NT*NBF];
__device__ float g_kp  [(long long)TT*HH*NC*NBF];
__device__ float g_ksum[TT*HH*NBF];
__device__ float g_kmxp[TT*HH*8];
__device__ float g_dinv[TT*HH*NT];
__device__ float g_ctx [(long long)TT*HH*NBF*DD];
__device__ float g_om  [TT*NT*HH*DD];           // merged [4096,2048]
__device__ float g_rep [TT*NT*DD];

// ---------------- generic tiled fp32 GEMM ----------------
// C[m,n] = alpha * sum_k A(m,k) * B(k,n) (+bias[n]) (relu) (*rowScale[m])
// TA: A stored [K,M] (A[k*lda+m]); else A[m*lda+k]
// TB: B stored [N,K] (B[n*ldb+k]); else B[k*ldb+n]
#define TM_ 64
#define TN_ 64
#define TK_ 16

template<bool TA, bool TB>
__global__ __launch_bounds__(256)
void gemm_kernel(const float* __restrict__ A, const float* __restrict__ B,
                 float* __restrict__ C,
                 int M, int N, int K, int lda, int ldb, int ldc, int cstride,
                 long long sA, long long sB, long long sC,
                 const float* __restrict__ bias, long long sBias,
                 const float* __restrict__ rowScale, long long sRS,
                 float alpha, int relu)
{
    __shared__ float As[TK_][TM_ + 1];
    __shared__ float Bs[TK_][TN_ + 1];

    int z = blockIdx.z;
    A += z * sA; B += z * sB; C += z * sC;
    const float* bptr = bias     ? bias     + z * sBias : nullptr;
    const float* rptr = rowScale ? rowScale + z * sRS   : nullptr;

    int tid = threadIdx.x;
    int tr = tid >> 4;       // 0..15
    int tc = tid & 15;       // 0..15
    int row0 = blockIdx.y * TM_;
    int col0 = blockIdx.x * TN_;

    float acc[4][4];
#pragma unroll
    for (int i = 0; i < 4; i++)
#pragma unroll
        for (int j = 0; j < 4; j++) acc[i][j] = 0.f;

    for (int k0 = 0; k0 < K; k0 += TK_) {
        // ---- load A tile: As[k][m] ----
#pragma unroll
        for (int it = 0; it < 4; ++it) {
            int idx = tid + it * 256;
            if (TA) {
                int kk = idx >> 6, m = idx & 63;
                int gm = row0 + m, gk = k0 + kk;
                As[kk][m] = (gm < M && gk < K) ? A[(long long)gk * lda + gm] : 0.f;
            } else {
                int m = idx >> 4, kk = idx & 15;
                int gm = row0 + m, gk = k0 + kk;
                As[kk][m] = (gm < M && gk < K) ? A[(long long)gm * lda + gk] : 0.f;
            }
        }
        // ---- load B tile: Bs[k][n] ----
#pragma unroll
        for (int it = 0; it < 4; ++it) {
            int idx = tid + it * 256;
            if (TB) {
                int n = idx >> 4, kk = idx & 15;
                int gn = col0 + n, gk = k0 + kk;
                Bs[kk][n] = (gn < N && gk < K) ? B[(long long)gn * ldb + gk] : 0.f;
            } else {
                int kk = idx >> 6, n = idx & 63;
                int gn = col0 + n, gk = k0 + kk;
                Bs[kk][n] = (gn < N && gk < K) ? B[(long long)gk * ldb + gn] : 0.f;
            }
        }
        __syncthreads();
#pragma unroll
        for (int kk = 0; kk < TK_; ++kk) {
            float a[4], b[4];
#pragma unroll
            for (int i = 0; i < 4; i++) a[i] = As[kk][tr * 4 + i];
#pragma unroll
            for (int j = 0; j < 4; j++) b[j] = Bs[kk][tc * 4 + j];
#pragma unroll
            for (int i = 0; i < 4; i++)
#pragma unroll
                for (int j = 0; j < 4; j++) acc[i][j] = fmaf(a[i], b[j], acc[i][j]);
        }
        __syncthreads();
    }

#pragma unroll
    for (int i = 0; i < 4; i++) {
        int r = row0 + tr * 4 + i;
        if (r >= M) continue;
        float rs = rptr ? rptr[r] : 1.f;
#pragma unroll
        for (int j = 0; j < 4; j++) {
            int c = col0 + tc * 4 + j;
            if (c >= N) continue;
            float v = acc[i][j] * alpha;
            if (bptr) v += bptr[c];
            if (relu) v = fmaxf(v, 0.f);
            v *= rs;
            C[(long long)r * ldc + (long long)c * cstride] = v;
        }
    }
}

// ---------------- reductions ----------------
__device__ __forceinline__ float block_reduce_sum(float v) {
    __shared__ float sh[32];
    int lane = threadIdx.x & 31, w = threadIdx.x >> 5;
#pragma unroll
    for (int o = 16; o; o >>= 1) v += __shfl_xor_sync(0xffffffffu, v, o);
    __syncthreads();
    if (lane == 0) sh[w] = v;
    __syncthreads();
    float r = (threadIdx.x < (blockDim.x >> 5)) ? sh[threadIdx.x] : 0.f;
    if (w == 0) {
#pragma unroll
        for (int o = 16; o; o >>= 1) r += __shfl_xor_sync(0xffffffffu, r, o);
        if (lane == 0) sh[0] = r;
    }
    __syncthreads();
    return sh[0];
}

__device__ __forceinline__ float block_reduce_max(float v) {
    __shared__ float sh[32];
    int lane = threadIdx.x & 31, w = threadIdx.x >> 5;
#pragma unroll
    for (int o = 16; o; o >>= 1) v = fmaxf(v, __shfl_xor_sync(0xffffffffu, v, o));
    __syncthreads();
    if (lane == 0) sh[w] = v;
    __syncthreads();
    float r = (threadIdx.x < (blockDim.x >> 5)) ? sh[threadIdx.x] : -INFINITY;
    if (w == 0) {
#pragma unroll
        for (int o = 16; o; o >>= 1) r = fmaxf(r, __shfl_xor_sync(0xffffffffu, r, o));
        if (lane == 0) sh[0] = r;
    }
    __syncthreads();
    return sh[0];
}

// ---------------- elementwise / feature kernels ----------------
__global__ void concat_kernel(const float* __restrict__ x, const float* __restrict__ lbl,
                              float* __restrict__ out) {
    int r = blockIdx.x, tid = threadIdx.x;  // 256 threads
    out[(long long)r * 259 + tid] = x[(long long)r * 256 + tid];
    if (tid < LBL) out[(long long)r * 259 + 256 + tid] = lbl[(long long)r * LBL + tid];
}

// queries: per-row max over F, diag from q row; in-place on dd
__global__ void qfeat_kernel(float* __restrict__ dd, const float* __restrict__ q) {
    long long row = blockIdx.x;
    const float* qr = q + row * DD;
    float* d = dd + row * NBF;
    int tid = threadIdx.x;  // 256
    float qv = qr[tid];
    float diag = 0.5f * block_reduce_sum(qv * qv) * DN2;
    float mx = -INFINITY;
    for (int f = tid; f < NBF; f += 256) mx = fmaxf(mx, d[f]);
    mx = block_reduce_max(mx);
    float sub = diag + mx;
    for (int f = tid; f < NBF; f += 256) d[f] = RATIO * (expf(d[f] - sub) + EPS_);
}

// keys stage 1: partial max per (t,h) over (n,f); 8 n-chunks of 64 rows
__global__ void kmax_kernel(const float* __restrict__ dd, float* __restrict__ kmaxp) {
    int th = blockIdx.y, chunk = blockIdx.x;
    const float* base = dd + ((long long)th * NC + (long long)chunk * 64) * NBF;
    float mx = -INFINITY;
    for (long long i = threadIdx.x; i < (long long)64 * NBF; i += blockDim.x)
        mx = fmaxf(mx, base[i]);
    mx = block_reduce_max(mx);
    if (threadIdx.x == 0) kmaxp[th * 8 + chunk] = mx;
}

// keys stage 2: apply exp with global-(t,h) max; in-place on dd
__global__ void kfeat_kernel(float* __restrict__ dd, const float* __restrict__ k,
                             const float* __restrict__ kmaxp) {
    long long row = blockIdx.x;
    int th = (int)(row >> 9);
    const float* kr = k + row * DD;
    float* d = dd + row * NBF;
    int tid = threadIdx.x;
    float kv = kr[tid];
    float diag = 0.5f * block_reduce_sum(kv * kv) * DN2;
    float mx = -INFINITY;
#pragma unroll
    for (int c = 0; c < 8; c++) mx = fmaxf(mx, kmaxp[th * 8 + c]);
    float sub = diag + mx;
    for (int f = tid; f < NBF; f += 256) d[f] = RATIO * (expf(d[f] - sub) + EPS_);
}

// ksum[th][f] = sum_n kp[th][n][f]
__global__ void ksum_kernel(const float* __restrict__ kp, float* __restrict__ ksum) {
    int th = blockIdx.x;
    const float* base = kp + (long long)th * NC * NBF;
    for (int f = threadIdx.x; f < NBF; f += blockDim.x) {
        float s = 0.f;
        for (int n = 0; n < NC; n++) s += base[(long long)n * NBF + f];
        ksum[(long long)th * NBF + f] = s;
    }
}

// d_inv[row] = 1 / dot(qp[row], ksum[th])
__global__ void dinv_kernel(const float* __restrict__ qp, const float* __restrict__ ksum,
                            float* __restrict__ dinv) {
    long long row = blockIdx.x;
    int th = (int)(row >> 9);
    const float* qr = qp + row * NBF;
    const float* ks = ksum + (long long)th * NBF;
    float s = 0.f;
    for (int f = threadIdx.x; f < NBF; f += 256) s += qr[f] * ks[f];
    s = block_reduce_sum(s);
    if (threadIdx.x == 0) dinv[row] = 1.0f / s;
}

// ---------------- host side ----------------
static float* symaddr(const void* sym) {
    void* p = nullptr;
    cudaGetSymbolAddress(&p, sym);
    return (float*)p;
}

static void gemm(bool ta, bool tb,
                 const float* A, const float* B, float* C,
                 int M, int N, int K, int lda, int ldb, int ldc, int cstride,
                 long long sA, long long sB, long long sC,
                 const float* bias, long long sBias,
                 const float* rs, long long sRS,
                 float alpha, int relu, int batch)
{
    dim3 grid((N + TN_ - 1) / TN_, (M + TM_ - 1) / TM_, batch), blk(256);
    if (!ta && !tb)
        gemm_kernel<false, false><<<grid, blk>>>(A, B, C, M, N, K, lda, ldb, ldc, cstride,
                                                 sA, sB, sC, bias, sBias, rs, sRS, alpha, relu);
    else if (!ta && tb)
        gemm_kernel<false, true><<<grid, blk>>>(A, B, C, M, N, K, lda, ldb, ldc, cstride,
                                                sA, sB, sC, bias, sBias, rs, sRS, alpha, relu);
    else if (ta && !tb)
        gemm_kernel<true, false><<<grid, blk>>>(A, B, C, M, N, K, lda, ldb, ldc, cstride,
                                                sA, sB, sC, bias, sBias, rs, sRS, alpha, relu);
    else
        gemm_kernel<true, true><<<grid, blk>>>(A, B, C, M, N, K, lda, ldb, ldc, cstride,
                                               sA, sB, sC, bias, sBias, rs, sRS, alpha, relu);
}

extern "C" void kernel_launch(void* const* d_in, const int* in_sizes, int n_in,
                              void* d_out, int out_size) {
    (void)in_sizes; (void)n_in; (void)out_size;
    const float* x_ctx = (const float*)d_in[0];
    const float* label = (const float*)d_in[1];
    const float* x_tgt = (const float*)d_in[2];
    const float* W1 = (const float*)d_in[3];  const float* b1 = (const float*)d_in[4];
    const float* W2 = (const float*)d_in[5];  const float* b2 = (const float*)d_in[6];
    const float* W3 = (const float*)d_in[7];  const float* b3 = (const float*)d_in[8];
    const float* Wk = (const float*)d_in[9];  const float* bk = (const float*)d_in[10];
    const float* Wv = (const float*)d_in[11]; const float* bv = (const float*)d_in[12];
    const float* Wq = (const float*)d_in[13]; const float* bq = (const float*)d_in[14];
    const float* Wo = (const float*)d_in[15]; const float* bo = (const float*)d_in[16];
    const float* Wmu = (const float*)d_in[17]; const float* bmu = (const float*)d_in[18];
    const float* proj = (const float*)d_in[19];
    float* out = (float*)d_out;

    float* xc   = symaddr(g_xc);
    float* h1   = symaddr(g_h1);
    float* h2   = symaddr(g_h2);
    float* cf   = symaddr(g_cf);
    float* kbuf = symaddr(g_k);
    float* vbuf = symaddr(g_v);
    float* qbuf = symaddr(g_q);
    float* qp   = symaddr(g_qp);
    float* kp   = symaddr(g_kp);
    float* ksum = symaddr(g_ksum);
    float* kmxp = symaddr(g_kmxp);
    float* dinv = symaddr(g_dinv);
    float* ctx  = symaddr(g_ctx);
    float* om   = symaddr(g_om);
    float* rep  = symaddr(g_rep);

    const int M_ALL = TT * NC;  // 4096

    // 1) task encoder MLP
    concat_kernel<<<M_ALL, 256>>>(x_ctx, label, xc);
    gemm(0, 0, xc, W1, h1, M_ALL, DD, DD + LBL, DD + LBL, DD, DD, 1, 0, 0, 0,
         b1, 0, nullptr, 0, 1.f, 1, 1);
    gemm(0, 0, h1, W2, h2, M_ALL, DD, DD, DD, DD, DD, 1, 0, 0, 0,
         b2, 0, nullptr, 0, 1.f, 1, 1);
    gemm(0, 0, h2, W3, cf, M_ALL, DD, DD, DD, DD, DD, 1, 0, 0, 0,
         b3, 0, nullptr, 0, 1.f, 1, 1);

    // 2) per-head k/v/q projections (layout [t,h,n,e]); batch over t, loop over h
    for (int h = 0; h < HH; h++) {
        long long wo = (long long)h * DD * DD;
        gemm(0, 0, x_ctx, Wk + wo, kbuf + (long long)h * NC * DD,
             NC, DD, DD, DD, DD, DD, 1,
             (long long)NC * DD, 0, (long long)HH * NC * DD,
             bk + h * DD, 0, nullptr, 0, 1.f, 0, TT);
        gemm(0, 0, cf, Wv + wo, vbuf + (long long)h * NC * DD,
             NC, DD, DD, DD, DD, DD, 1,
             (long long)NC * DD, 0, (long long)HH * NC * DD,
             bv + h * DD, 0, nullptr, 0, 1.f, 0, TT);
        gemm(0, 0, x_tgt, Wq + wo, qbuf + (long long)h * NT * DD,
             NT, DD, DD, DD, DD, DD, 1,
             (long long)NT * DD, 0, (long long)HH * NT * DD,
             bq + h * DD, 0, nullptr, 0, 1.f, 0, TT);
    }

    // 3) FAVOR+ feature projections: dd = (x * dn) @ proj^T, batch over (t,h)
    gemm(0, 1, qbuf, proj, qp, NT, NBF, DD, DD, DD, NBF, 1,
         (long long)NT * DD, 0, (long long)NT * NBF,
         nullptr, 0, nullptr, 0, DN, 0, TT * HH);
    gemm(0, 1, kbuf, proj, kp, NC, NBF, DD, DD, DD, NBF, 1,
         (long long)NC * DD, 0, (long long)NC * NBF,
         nullptr, 0, nullptr, 0, DN, 0, TT * HH);

    // 4) softmax-kernel transforms
    kmax_kernel<<<dim3(8, TT * HH), 256>>>(kp, kmxp);
    qfeat_kernel<<<TT * HH * NT, 256>>>(qp, qbuf);
    kfeat_kernel<<<TT * HH * NC, 256>>>(kp, kbuf, kmxp);
    ksum_kernel<<<TT * HH, 512>>>(kp, ksum);
    dinv_kernel<<<TT * HH * NT, 256>>>(qp, ksum, dinv);

    // 5) ctx[t,h] = kp^T @ v : [1419,256] = [512,1419]^T @ [512,256], batch 64
    gemm(1, 0, kp, vbuf, ctx, NBF, DD, NC, NBF, DD, DD, 1,
         (long long)NC * NBF, (long long)NC * DD, (long long)NBF * DD,
         nullptr, 0, nullptr, 0, 1.f, 0, TT * HH);

    // 6) out = (qp @ ctx) * d_inv, stored head-interleaved into om[t,n,e*H+h]
    for (int h = 0; h < HH; h++) {
        gemm(0, 0, qp + (long long)h * NT * NBF, ctx + (long long)h * NBF * DD, om + h,
             NT, DD, NBF, NBF, DD, HH * DD, HH,
             (long long)HH * NT * NBF, (long long)HH * NBF * DD, (long long)NT * HH * DD,
             nullptr, 0, dinv + (long long)h * NT, (long long)HH * NT, 1.f, 0, TT);
    }

    // 7) rep = om @ Wo + bo ; mu = rep @ Wmu + bmu
    gemm(0, 0, om, Wo, rep, M_ALL, DD, HH * DD, HH * DD, DD, DD, 1,
         0, 0, 0, bo, 0, nullptr, 0, 1.f, 0, 1);
    gemm(0, 0, rep, Wmu, out, M_ALL, DD, DD, DD, DD, DD, 1,
         0, 0, 0, bmu, 0, nullptr, 0, 1.f, 0, 1);
}